// round 14
// baseline (speedup 1.0000x reference)
#include <cuda_runtime.h>
#include <cuda_fp16.h>
#include <math.h>
#include <stdint.h>

// ---------------------------------------------------------------------------
// Problem constants
#define BN_   256
#define TN_   256
#define DN_   300
#define HN_   512
#define XPAD  320
#define KPAD  832
#define NCHX  5
#define NCHS  8
#define FOURH 2048

// ---------------------------------------------------------------------------
// Scratch (device globals)
__device__ __half g_xhi[2ll * BN_ * TN_ * XPAD];
__device__ __half g_xlo[2ll * BN_ * TN_ * XPAD];
__device__ __half g_whi[4ll * FOURH * KPAD];
__device__ float  g_bp [4 * FOURH];
__device__ __half g_hhi[2ll * 4 * BN_ * HN_];
__device__ __half g_hlo[2ll * 4 * BN_ * HN_];
__device__ float  g_c  [4][BN_][HN_];
__device__ float  g_x  [BN_ * FOURH];
__device__ float  g_m1[BN_ * 1024];
__device__ float  g_m2[BN_ * 1024];
__device__ float  g_m3[BN_ * 1024];

#define XZ_PER (2ll * TN_ * BN_ * FOURH)
__device__ float g_xzA[XZ_PER];
__device__ float g_xzB[XZ_PER];

__device__ __forceinline__ float sig_(float x) {
    return __fdividef(1.0f, 1.0f + __expf(-x));
}
__device__ __forceinline__ float tanh_(float x) {
    float ax = fabsf(x);
    float e  = __expf(-2.0f * ax);
    float r  = __fdividef(1.0f - e, 1.0f + e);
    return copysignf(r, x);
}

__device__ __forceinline__ uint32_t smem_u32(const void* p) {
    uint32_t a;
    asm("{ .reg .u64 t; cvta.to.shared.u64 t, %1; cvt.u32.u64 %0, t; }" : "=r"(a) : "l"(p));
    return a;
}
__device__ __forceinline__ void cp16(uint32_t dst, const void* src) {
    asm volatile("cp.async.cg.shared.global [%0], [%1], 16;" :: "r"(dst), "l"(src));
}
#define CP_COMMIT() asm volatile("cp.async.commit_group;" ::: "memory")
#define CP_WAIT(N)  asm volatile("cp.async.wait_group %0;" :: "n"(N) : "memory")

#define LDSM_X4(r0, r1, r2, r3, addr)                                         \
    asm volatile("ldmatrix.sync.aligned.m8n8.x4.shared.b16 {%0,%1,%2,%3}, [%4];" \
        : "=r"(r0), "=r"(r1), "=r"(r2), "=r"(r3) : "r"(addr))

#define MMA16816(d, a, b)                                                     \
    asm volatile("mma.sync.aligned.m16n8k16.row.col.f32.f16.f16.f32 "         \
        "{%0,%1,%2,%3}, {%4,%5,%6,%7}, {%8,%9}, {%0,%1,%2,%3};"               \
        : "+f"((d)[0]), "+f"((d)[1]), "+f"((d)[2]), "+f"((d)[3])              \
        : "r"((a)[0]), "r"((a)[1]), "r"((a)[2]), "r"((a)[3]),                 \
          "r"((b)[0]), "r"((b)[1]))

#define MMA16816H(d, a, b)                                                    \
    asm volatile("mma.sync.aligned.m16n8k16.row.col.f16.f16.f16.f16 "         \
        "{%0,%1}, {%2,%3,%4,%5}, {%6,%7}, {%0,%1};"                           \
        : "+r"((d)[0]), "+r"((d)[1])                                          \
        : "r"((a)[0]), "r"((a)[1]), "r"((a)[2]), "r"((a)[3]),                 \
          "r"((b)[0]), "r"((b)[1]))

// ---------------------------------------------------------------------------
struct WPtrs { const float* wx[4]; const float* wh[4]; const float* bias[4]; };

#define NXE_ (2ll * BN_ * TN_ * XPAD)
#define NWE_ (4ll * FOURH * KPAD)
#define NHE_ (2ll * 4 * BN_ * HN_)
#define NCE_ (4ll * BN_ * HN_)
#define NBE_ (4ll * FOURH)
#define NTOT_ (NXE_ + NWE_ + NHE_ + NCE_ + NBE_)

__global__ void preproc_all(const float* __restrict__ prem, const float* __restrict__ hyp,
                            WPtrs wp) {
    long long i = (long long)blockIdx.x * blockDim.x + threadIdx.x;
    if (i < NXE_) {
        int k = (int)(i % XPAD);
        long long r = i / XPAD;
        int t = (int)(r % TN_); r /= TN_;
        int b = (int)(r % BN_);
        int inp = (int)(r / BN_);
        float v = 0.0f;
        if (k < DN_) {
            const float* src = inp ? hyp : prem;
            v = src[((long long)b * TN_ + t) * DN_ + k];
        }
        __half h = __float2half(v);
        g_xhi[i] = h;
        g_xlo[i] = __float2half(v - __half2float(h));
        return;
    }
    i -= NXE_;
    if (i < NWE_) {
        int kp = (int)(i % KPAD);
        long long r = i / KPAD;
        int c   = (int)(r % FOURH);
        int seq = (int)(r / FOURH);
        int oc  = (c & 3) * HN_ + (c >> 2);
        float v = 0.0f;
        if (kp < DN_)        v = wp.wx[seq][(long long)kp * FOURH + oc];
        else if (kp >= XPAD) v = wp.wh[seq][(long long)(kp - XPAD) * FOURH + oc];
        g_whi[i] = __float2half(v);
        return;
    }
    i -= NWE_;
    if (i < NHE_) {
        g_hhi[i] = __float2half(0.f);
        g_hlo[i] = __float2half(0.f);
        return;
    }
    i -= NHE_;
    if (i < NCE_) {
        (&g_c[0][0][0])[i] = 0.0f;
        return;
    }
    i -= NCE_;
    if (i < NBE_) {
        int c = (int)(i & (FOURH - 1));
        int seq = (int)(i >> 11);
        g_bp[i] = wp.bias[seq][(c & 3) * HN_ + (c >> 2)];
    }
}

// ---------------------------------------------------------------------------
// xz precompute GEMM, 2-product (unchanged from R12)
#define XST_BYTES 40960
#define XOFF_AL   16384
#define XOFF_BH   32768
#define SMEM_XZ   81920

__global__ __launch_bounds__(256) void xz_gemm() {
    extern __shared__ char smem[];
    const uint32_t sbase = smem_u32(smem);
    const int tid  = threadIdx.x;
    const int lane = tid & 31;
    const int wid  = tid >> 5;
    const int warp_m = wid >> 1;
    const int warp_n = wid & 1;

    const int z   = blockIdx.z;
    const int seq = z >> 8;
    const int t   = z & 255;
    const int inp = seq >> 1;
    const int b0  = blockIdx.y * 128;
    const int n0  = blockIdx.x * 64;

    auto load_chunk = [&](int k, int p) {
        const uint32_t st = sbase + (p ? XST_BYTES : 0);
        const int k0 = k * 64;
        #pragma unroll
        for (int j = 0; j < 4; j++) {
            int idx = tid + 256 * j;
            int row = idx >> 3;
            int seg = idx & 7;
            long base = ((long)(inp * BN_ + b0 + row) * TN_ + t) * XPAD + k0 + seg * 8;
            uint32_t dst = st + ((row * 8 + (seg ^ (row & 7))) << 4);
            cp16(dst,           g_xhi + base);
            cp16(dst + XOFF_AL, g_xlo + base);
        }
        #pragma unroll
        for (int j = 0; j < 2; j++) {
            int idx = tid + 256 * j;
            int row = idx >> 3;
            int seg = idx & 7;
            long base = ((long)seq * FOURH + n0 + row) * KPAD + k0 + seg * 8;
            uint32_t dst = st + XOFF_BH + ((row * 8 + (seg ^ (row & 7))) << 4);
            cp16(dst, g_whi + base);
        }
        CP_COMMIT();
    };

    float acc[2][4][4];
    uint32_t acch[2][4][2];
    #pragma unroll
    for (int mi = 0; mi < 2; mi++)
        #pragma unroll
        for (int ni = 0; ni < 4; ni++) {
            #pragma unroll
            for (int q = 0; q < 4; q++) acc[mi][ni][q] = 0.0f;
            acch[mi][ni][0] = 0u; acch[mi][ni][1] = 0u;
        }

    int arowb[2], arowx[2];
    #pragma unroll
    for (int mi = 0; mi < 2; mi++) {
        int r = warp_m * 32 + mi * 16 + (lane & 15);
        arowb[mi] = r * 128;
        arowx[mi] = r & 7;
    }
    int brow[2], browx[2];
    #pragma unroll
    for (int np = 0; np < 2; np++) {
        int n = warp_n * 32 + np * 16 + ((lane >> 4) << 3) + (lane & 7);
        brow[np]  = n * 128;
        browx[np] = n & 7;
    }
    const int asel = lane >> 4;
    const int bsel = (lane >> 3) & 1;

    load_chunk(0, 0);

    for (int k = 0; k < NCHX; k++) {
        const int p = k & 1;
        if (k + 1 < NCHX) load_chunk(k + 1, p ^ 1);
        if (k + 1 < NCHX) CP_WAIT(1); else CP_WAIT(0);
        __syncthreads();

        const uint32_t st = sbase + (p ? XST_BYTES : 0);
        #pragma unroll
        for (int kk = 0; kk < 4; kk++) {
            uint32_t ah[2][4], al[2][4];
            #pragma unroll
            for (int mi = 0; mi < 2; mi++) {
                int seg = 2 * kk + asel;
                uint32_t off = arowb[mi] + ((seg ^ arowx[mi]) << 4);
                LDSM_X4(ah[mi][0], ah[mi][1], ah[mi][2], ah[mi][3], st + off);
                LDSM_X4(al[mi][0], al[mi][1], al[mi][2], al[mi][3], st + XOFF_AL + off);
            }
            uint32_t bh[2][4];
            #pragma unroll
            for (int np = 0; np < 2; np++) {
                int seg = 2 * kk + bsel;
                uint32_t off = brow[np] + ((seg ^ browx[np]) << 4);
                LDSM_X4(bh[np][0], bh[np][1], bh[np][2], bh[np][3], st + XOFF_BH + off);
            }
            #pragma unroll
            for (int mi = 0; mi < 2; mi++)
                #pragma unroll
                for (int np = 0; np < 2; np++)
                    #pragma unroll
                    for (int h = 0; h < 2; h++) {
                        int ni = np * 2 + h;
                        uint32_t bhf[2] = { bh[np][2 * h], bh[np][2 * h + 1] };
                        MMA16816 (acc[mi][ni],  ah[mi], bhf);
                        MMA16816H(acch[mi][ni], al[mi], bhf);
                    }
        }
        __syncthreads();
    }

    float* xz = (seq < 2) ? g_xzA : g_xzB;
    const long zb = ((long)(seq & 1) * TN_ + t) * BN_;
    #pragma unroll
    for (int mi = 0; mi < 2; mi++) {
        #pragma unroll
        for (int ni = 0; ni < 4; ni++) {
            float2 c01 = __half22float2(*(__half2*)&acch[mi][ni][0]);
            float2 c23 = __half22float2(*(__half2*)&acch[mi][ni][1]);
            int col = n0 + warp_n * 32 + ni * 8 + 2 * (lane & 3);
            int r0  = b0 + warp_m * 32 + mi * 16 + (lane >> 2);
            float2 v01 = make_float2(acc[mi][ni][0] + c01.x, acc[mi][ni][1] + c01.y);
            float2 v23 = make_float2(acc[mi][ni][2] + c23.x, acc[mi][ni][3] + c23.y);
            *(float2*)&xz[(zb + r0)     * FOURH + col] = v01;
            *(float2*)&xz[(zb + r0 + 8) * FOURH + col] = v23;
        }
    }
}

// ---------------------------------------------------------------------------
// Per-step LSTM, 2-product MMA, 3-stage pipeline (ONE sync per chunk),
// direct-global epilogue. 512 threads, 16 warps (4m x 4n).
// SMEM: stage = Ah(16K)|Al(16K)|Bh(16K) = 48KB x 3 stages @0/49152/98304;
//   xz @147456 (65536B -> ends 212992); bias @212992; len @213504.
//   Total 214016 (<= 227KB). z buffer (phase1) reuses [0, 65536).
#define ST_BYTES 49152
#define OFF_AL   16384
#define OFF_BH   32768
#define OFF_XZ   147456
#define OFF_BIAS 212992
#define OFF_LEN  213504
#define SMEM_TOTAL_STEP 214016

__global__ __launch_bounds__(512) void lstm_step_mma(const int* __restrict__ plen,
                                                     const int* __restrict__ hlen,
                                                     int s) {
    extern __shared__ char smem[];
    const uint32_t sbase = smem_u32(smem);
    const int tid  = threadIdx.x;
    const int lane = tid & 31;
    const int wid  = tid >> 5;
    const int warp_m = wid >> 2;
    const int warp_n = wid & 3;

    const int seq = blockIdx.z;
    const int rev = seq & 1;
    const int t   = rev ? (TN_ - 1 - s) : s;
    const int b0  = blockIdx.y * 128;
    const int n0  = blockIdx.x * 128;
    const int u0  = n0 >> 2;
    const int cur = s & 1;

    const int* __restrict__ len = (seq < 2) ? plen : hlen;
    if (tid < 128) {
        *(float*)(smem + OFF_BIAS + tid * 4) = g_bp[seq * FOURH + n0 + tid];
        *(int*)(smem + OFF_LEN + tid * 4) = len[b0 + tid];
    }

    const long hin_base  = ((long)cur * 4 + seq) * (BN_ * HN_);
    const long hout_base = ((long)(cur ^ 1) * 4 + seq) * (BN_ * HN_);
    const float* __restrict__ xzg = (seq < 2) ? g_xzA : g_xzB;
    const long zb = ((long)(seq & 1) * TN_ + t) * BN_;

    auto load_chunk = [&](int k, int stg) {
        const uint32_t st = sbase + stg * ST_BYTES;
        const int k0 = k * 64;
        #pragma unroll
        for (int j = 0; j < 2; j++) {           // A = h: hi + lo
            int idx = tid + 512 * j;
            int row = idx >> 3;
            int seg = idx & 7;
            long base = hin_base + (long)(b0 + row) * HN_ + k0 + seg * 8;
            uint32_t dst = st + ((row * 8 + (seg ^ (row & 7))) << 4);
            cp16(dst,          g_hhi + base);
            cp16(dst + OFF_AL, g_hlo + base);
        }
        #pragma unroll
        for (int j = 0; j < 2; j++) {           // B = Wh region: hi only
            int idx = tid + 512 * j;
            int row = idx >> 3;
            int seg = idx & 7;
            long base = ((long)seq * FOURH + n0 + row) * KPAD + XPAD + k0 + seg * 8;
            uint32_t dst = st + OFF_BH + ((row * 8 + (seg ^ (row & 7))) << 4);
            cp16(dst, g_whi + base);
        }
        // xz piece k: 16 rows x 128 cols fp32 (1 seg/thread)
        {
            int row = (k << 4) + (tid >> 5);
            int seg = tid & 31;
            const float* src = xzg + (zb + b0 + row) * FOURH + n0 + seg * 4;
            cp16(sbase + OFF_XZ + row * 512 + seg * 16, src);
        }
        CP_COMMIT();
    };

    float acc[2][4][4];
    uint32_t acch[2][4][2];
    #pragma unroll
    for (int mi = 0; mi < 2; mi++)
        #pragma unroll
        for (int ni = 0; ni < 4; ni++) {
            #pragma unroll
            for (int q = 0; q < 4; q++) acc[mi][ni][q] = 0.0f;
            acch[mi][ni][0] = 0u; acch[mi][ni][1] = 0u;
        }

    int arowb[2], arowx[2];
    #pragma unroll
    for (int mi = 0; mi < 2; mi++) {
        int r = warp_m * 32 + mi * 16 + (lane & 15);
        arowb[mi] = r * 128;
        arowx[mi] = r & 7;
    }
    int brow[2], browx[2];
    #pragma unroll
    for (int np = 0; np < 2; np++) {
        int n = warp_n * 32 + np * 16 + ((lane >> 4) << 3) + (lane & 7);
        brow[np]  = n * 128;
        browx[np] = n & 7;
    }
    const int asel = lane >> 4;
    const int bsel = (lane >> 3) & 1;

    load_chunk(0, 0);
    load_chunk(1, 1);

    for (int k = 0; k < NCHS; k++) {
        // wait own groups (chunk k complete), barrier for cross-thread
        // visibility and to guarantee stage (k+2)%3 is idle before reuse.
        if (k + 1 < NCHS) { CP_WAIT(1); } else { CP_WAIT(0); }
        __syncthreads();
        if (k + 2 < NCHS) load_chunk(k + 2, (k + 2) % 3);

        const uint32_t st = sbase + (k % 3) * ST_BYTES;
        #pragma unroll
        for (int kk = 0; kk < 4; kk++) {
            uint32_t ah[2][4], al[2][4];
            #pragma unroll
            for (int mi = 0; mi < 2; mi++) {
                int seg = 2 * kk + asel;
                uint32_t off = arowb[mi] + ((seg ^ arowx[mi]) << 4);
                LDSM_X4(ah[mi][0], ah[mi][1], ah[mi][2], ah[mi][3], st + off);
                LDSM_X4(al[mi][0], al[mi][1], al[mi][2], al[mi][3], st + OFF_AL + off);
            }
            uint32_t bh[2][4];
            #pragma unroll
            for (int np = 0; np < 2; np++) {
                int seg = 2 * kk + bsel;
                uint32_t off = brow[np] + ((seg ^ browx[np]) << 4);
                LDSM_X4(bh[np][0], bh[np][1], bh[np][2], bh[np][3], st + OFF_BH + off);
            }
            #pragma unroll
            for (int mi = 0; mi < 2; mi++)
                #pragma unroll
                for (int np = 0; np < 2; np++)
                    #pragma unroll
                    for (int h = 0; h < 2; h++) {
                        int ni = np * 2 + h;
                        uint32_t bhf[2] = { bh[np][2 * h], bh[np][2 * h + 1] };
                        MMA16816 (acc[mi][ni],  ah[mi], bhf);
                        MMA16816H(acch[mi][ni], al[mi], bhf);
                    }
        }
    }
    __syncthreads();   // all warps done reading stages before z-buffer reuse

    // ---- phase 1: fragments -> swizzled z buffer [0, 64K) -----------------
    #pragma unroll
    for (int mi = 0; mi < 2; mi++) {
        #pragma unroll
        for (int ni = 0; ni < 4; ni++) {
            float2 c01 = __half22float2(*(__half2*)&acch[mi][ni][0]);
            float2 c23 = __half22float2(*(__half2*)&acch[mi][ni][1]);
            int col = warp_n * 32 + ni * 8 + 2 * (lane & 3);
            int rl0 = warp_m * 32 + mi * 16 + (lane >> 2);
            float2 v01 = make_float2(acc[mi][ni][0] + c01.x, acc[mi][ni][1] + c01.y);
            float2 v23 = make_float2(acc[mi][ni][2] + c23.x, acc[mi][ni][3] + c23.y);
            int g  = col >> 2;
            int ob = (col & 3) * 4;
            *(float2*)(smem + rl0 * 512 + (((g ^ (rl0 & 7)) << 4) | ob)) = v01;
            int rl1 = rl0 + 8;
            *(float2*)(smem + rl1 * 512 + (((g ^ (rl1 & 7)) << 4) | ob)) = v23;
        }
    }
    __syncthreads();

    // ---- phase 2: all 512 threads, 8 elements each; direct global I/O -----
    const float* bias_s = (const float*)(smem + OFF_BIAS);
    const int*   len_s  = (const int*)(smem + OFF_LEN);

    #pragma unroll
    for (int it = 0; it < 8; it++) {
        int e   = it * 512 + tid;
        int row = e >> 5;            // batch row within tile
        int u   = e & 31;            // hidden unit within tile
        float4 zv = *(const float4*)(smem + row * 512 + ((u ^ (row & 7)) << 4));
        float4 xv = *(const float4*)(smem + OFF_XZ + row * 512 + u * 16);
        float4 bv = *(const float4*)(bias_s + 4 * u);
        float iv = zv.x + xv.x + bv.x;
        float jv = zv.y + xv.y + bv.y;
        float fv = zv.z + xv.z + bv.z;
        float ov = zv.w + xv.w + bv.w;
        bool  m  = (t < len_s[row]);
        long  ci = (long)(b0 + row) * HN_ + u0 + u;
        float c_old = (&g_c[0][0][0])[(long)seq * BN_ * HN_ + ci];
        float nc = c_old * sig_(fv + 1.0f) + sig_(iv) * tanh_(jv);
        float nh = tanh_(nc) * sig_(ov);
        (&g_c[0][0][0])[(long)seq * BN_ * HN_ + ci] = m ? nc : c_old;
        __half hh, hl;
        if (m) {
            hh = __float2half(nh);
            hl = __float2half(nh - __half2float(hh));
        } else {
            hh = g_hhi[hin_base + ci];
            hl = g_hlo[hin_base + ci];
        }
        g_hhi[hout_base + ci] = hh;
        g_hlo[hout_base + ci] = hl;
    }
}

// ---------------------------------------------------------------------------
// MLP head (fp32)
__global__ void gather_x_kernel() {
    int i = blockIdx.x * blockDim.x + threadIdx.x;
    if (i >= BN_ * FOURH) return;
    int b   = i >> 11;
    int col = i & 2047;
    g_x[i] = g_c[col >> 9][b][col & 511];
}

#define BMT 64
#define BUT 64
#define KT  16
__global__ __launch_bounds__(256) void mlp_gemm_kernel(const float* __restrict__ W,
                                                       const float* __restrict__ bias,
                                                       int layer) {
    const float* A; float* C; int K, N;
    if (layer == 1)      { A = g_x;  C = g_m1; K = 2048; N = 1024; }
    else if (layer == 2) { A = g_m1; C = g_m2; K = 1024; N = 1024; }
    else                 { A = g_m2; C = g_m3; K = 1024; N = 1024; }

    const int m0 = blockIdx.y * BMT;
    const int n0 = blockIdx.x * BUT;
    __shared__ float As[KT][BMT];
    __shared__ float Bs[KT][BUT];
    const int tid = threadIdx.x;
    const int r0  = (tid >> 4) * 4;
    const int nt0 = (tid & 15) * 4;

    float acc[4][4];
    #pragma unroll
    for (int r = 0; r < 4; r++)
        #pragma unroll
        for (int u = 0; u < 4; u++) acc[r][u] = 0.0f;

    for (int k0 = 0; k0 < K; k0 += KT) {
        {
            int r  = tid >> 2;
            int kq = (tid & 3) * 4;
            #pragma unroll
            for (int i = 0; i < 4; i++)
                As[kq + i][r] = A[(m0 + r) * K + k0 + kq + i];
        }
        {
            int kk = tid >> 4;
            int uu = (tid & 15) * 4;
            *(float4*)&Bs[kk][uu] = *(const float4*)(W + (k0 + kk) * N + n0 + uu);
        }
        __syncthreads();
        #pragma unroll
        for (int kk = 0; kk < KT; kk++) {
            float4 a4 = *(const float4*)&As[kk][r0];
            float4 b4 = *(const float4*)&Bs[kk][nt0];
            float av[4] = {a4.x, a4.y, a4.z, a4.w};
            float bv[4] = {b4.x, b4.y, b4.z, b4.w};
            #pragma unroll
            for (int r = 0; r < 4; r++)
                #pragma unroll
                for (int u = 0; u < 4; u++)
                    acc[r][u] = fmaf(av[r], bv[u], acc[r][u]);
        }
        __syncthreads();
    }
    #pragma unroll
    for (int r = 0; r < 4; r++)
        #pragma unroll
        for (int u = 0; u < 4; u++) {
            int n = n0 + nt0 + u;
            C[(m0 + r0 + r) * N + n] = tanhf(acc[r][u] + bias[n]);
        }
}

__global__ void final_logits_kernel(const float* __restrict__ W4,
                                    const float* __restrict__ b4,
                                    float* __restrict__ out) {
    int b    = blockIdx.x;
    int w    = threadIdx.x >> 5;
    int lane = threadIdx.x & 31;
    if (w >= 3) return;
    float sum = 0.0f;
    for (int k = lane; k < 1024; k += 32)
        sum += g_m3[b * 1024 + k] * W4[k * 3 + w];
    #pragma unroll
    for (int off = 16; off; off >>= 1)
        sum += __shfl_down_sync(0xffffffff, sum, off);
    if (lane == 0) out[b * 3 + w] = sum + b4[w];
}

// ---------------------------------------------------------------------------
extern "C" void kernel_launch(void* const* d_in, const int* in_sizes, int n_in,
                              void* d_out, int out_size) {
    const float* premises   = (const float*)d_in[0];
    const float* hypotheses = (const float*)d_in[1];
    const int*   plen       = (const int*)d_in[2];
    const int*   hlen       = (const int*)d_in[3];

    WPtrs wp;
    for (int i = 0; i < 4; i++) {
        wp.wx[i]   = (const float*)d_in[4 + 3 * i + 0];
        wp.wh[i]   = (const float*)d_in[4 + 3 * i + 1];
        wp.bias[i] = (const float*)d_in[4 + 3 * i + 2];
    }
    const float* W1 = (const float*)d_in[16];
    const float* b1 = (const float*)d_in[17];
    const float* W2 = (const float*)d_in[18];
    const float* b2 = (const float*)d_in[19];
    const float* W3 = (const float*)d_in[20];
    const float* b3 = (const float*)d_in[21];
    const float* W4 = (const float*)d_in[22];
    const float* b4 = (const float*)d_in[23];
    float* out = (float*)d_out;

    cudaFuncSetAttribute(lstm_step_mma, cudaFuncAttributeMaxDynamicSharedMemorySize,
                         SMEM_TOTAL_STEP);
    cudaFuncSetAttribute(xz_gemm, cudaFuncAttributeMaxDynamicSharedMemorySize,
                         SMEM_XZ);

    {
        long long n = NTOT_;
        preproc_all<<<(unsigned)((n + 255) / 256), 256>>>(premises, hypotheses, wp);
    }

    xz_gemm<<<dim3(32, 2, 4 * TN_), 256, SMEM_XZ>>>();

    dim3 grid(16, 2, 4);
    for (int s = 0; s < TN_; s++)
        lstm_step_mma<<<grid, 512, SMEM_TOTAL_STEP>>>(plen, hlen, s);

    gather_x_kernel<<<(BN_ * FOURH + 255) / 256, 256>>>();
    mlp_gemm_kernel<<<dim3(1024 / BUT, BN_ / BMT), 256>>>(W1, b1, 1);
    mlp_gemm_kernel<<<dim3(1024 / BUT, BN_ / BMT), 256>>>(W2, b2, 2);
    mlp_gemm_kernel<<<dim3(1024 / BUT, BN_ / BMT), 256>>>(W3, b3, 3);
    final_logits_kernel<<<BN_, 96>>>(W4, b4, out);
}

// round 15
// speedup vs baseline: 1.0334x; 1.0334x over previous
#include <cuda_runtime.h>
#include <cuda_fp16.h>
#include <math.h>
#include <stdint.h>

// ---------------------------------------------------------------------------
// Problem constants
#define BN_   256
#define TN_   256
#define DN_   300
#define HN_   512
#define XPAD  320
#define KPAD  832
#define NCHX  5
#define NCHS  8
#define FOURH 2048

// ---------------------------------------------------------------------------
// Scratch (device globals)
__device__ __half g_xhi[2ll * BN_ * TN_ * XPAD];
__device__ __half g_xlo[2ll * BN_ * TN_ * XPAD];
__device__ __half g_whi[4ll * FOURH * KPAD];
__device__ float  g_bp [4 * FOURH];
__device__ __half g_hhi[2ll * 4 * BN_ * HN_];
__device__ __half g_hlo[2ll * 4 * BN_ * HN_];
__device__ float  g_c  [4][BN_][HN_];
__device__ float  g_x  [BN_ * FOURH];
__device__ float  g_m1[BN_ * 1024];
__device__ float  g_m2[BN_ * 1024];
__device__ float  g_m3[BN_ * 1024];

#define XZ_PER (2ll * TN_ * BN_ * FOURH)
__device__ float g_xzA[XZ_PER];
__device__ float g_xzB[XZ_PER];

__device__ __forceinline__ float sig_(float x) {
    return __fdividef(1.0f, 1.0f + __expf(-x));
}
__device__ __forceinline__ float tanh_(float x) {
    float ax = fabsf(x);
    float e  = __expf(-2.0f * ax);
    float r  = __fdividef(1.0f - e, 1.0f + e);
    return copysignf(r, x);
}

__device__ __forceinline__ uint32_t smem_u32(const void* p) {
    uint32_t a;
    asm("{ .reg .u64 t; cvta.to.shared.u64 t, %1; cvt.u32.u64 %0, t; }" : "=r"(a) : "l"(p));
    return a;
}
__device__ __forceinline__ void cp16(uint32_t dst, const void* src) {
    asm volatile("cp.async.cg.shared.global [%0], [%1], 16;" :: "r"(dst), "l"(src));
}
#define CP_COMMIT() asm volatile("cp.async.commit_group;" ::: "memory")
#define CP_WAIT(N)  asm volatile("cp.async.wait_group %0;" :: "n"(N) : "memory")

#define LDSM_X4(r0, r1, r2, r3, addr)                                         \
    asm volatile("ldmatrix.sync.aligned.m8n8.x4.shared.b16 {%0,%1,%2,%3}, [%4];" \
        : "=r"(r0), "=r"(r1), "=r"(r2), "=r"(r3) : "r"(addr))

#define MMA16816(d, a, b)                                                     \
    asm volatile("mma.sync.aligned.m16n8k16.row.col.f32.f16.f16.f32 "         \
        "{%0,%1,%2,%3}, {%4,%5,%6,%7}, {%8,%9}, {%0,%1,%2,%3};"               \
        : "+f"((d)[0]), "+f"((d)[1]), "+f"((d)[2]), "+f"((d)[3])              \
        : "r"((a)[0]), "r"((a)[1]), "r"((a)[2]), "r"((a)[3]),                 \
          "r"((b)[0]), "r"((b)[1]))

#define MMA16816H(d, a, b)                                                    \
    asm volatile("mma.sync.aligned.m16n8k16.row.col.f16.f16.f16.f16 "         \
        "{%0,%1}, {%2,%3,%4,%5}, {%6,%7}, {%0,%1};"                           \
        : "+r"((d)[0]), "+r"((d)[1])                                          \
        : "r"((a)[0]), "r"((a)[1]), "r"((a)[2]), "r"((a)[3]),                 \
          "r"((b)[0]), "r"((b)[1]))

// ---------------------------------------------------------------------------
struct WPtrs { const float* wx[4]; const float* wh[4]; const float* bias[4]; };

#define NXE_ (2ll * BN_ * TN_ * XPAD)
#define NWE_ (4ll * FOURH * KPAD)
#define NHE_ (2ll * 4 * BN_ * HN_)
#define NCE_ (4ll * BN_ * HN_)
#define NBE_ (4ll * FOURH)
#define NTOT_ (NXE_ + NWE_ + NHE_ + NCE_ + NBE_)

__global__ void preproc_all(const float* __restrict__ prem, const float* __restrict__ hyp,
                            WPtrs wp) {
    long long i = (long long)blockIdx.x * blockDim.x + threadIdx.x;
    if (i < NXE_) {
        int k = (int)(i % XPAD);
        long long r = i / XPAD;
        int t = (int)(r % TN_); r /= TN_;
        int b = (int)(r % BN_);
        int inp = (int)(r / BN_);
        float v = 0.0f;
        if (k < DN_) {
            const float* src = inp ? hyp : prem;
            v = src[((long long)b * TN_ + t) * DN_ + k];
        }
        __half h = __float2half(v);
        g_xhi[i] = h;
        g_xlo[i] = __float2half(v - __half2float(h));
        return;
    }
    i -= NXE_;
    if (i < NWE_) {
        int kp = (int)(i % KPAD);
        long long r = i / KPAD;
        int c   = (int)(r % FOURH);
        int seq = (int)(r / FOURH);
        int oc  = (c & 3) * HN_ + (c >> 2);
        float v = 0.0f;
        if (kp < DN_)        v = wp.wx[seq][(long long)kp * FOURH + oc];
        else if (kp >= XPAD) v = wp.wh[seq][(long long)(kp - XPAD) * FOURH + oc];
        g_whi[i] = __float2half(v);
        return;
    }
    i -= NWE_;
    if (i < NHE_) {
        g_hhi[i] = __float2half(0.f);
        g_hlo[i] = __float2half(0.f);
        return;
    }
    i -= NHE_;
    if (i < NCE_) {
        (&g_c[0][0][0])[i] = 0.0f;
        return;
    }
    i -= NCE_;
    if (i < NBE_) {
        int c = (int)(i & (FOURH - 1));
        int seq = (int)(i >> 11);
        g_bp[i] = wp.bias[seq][(c & 3) * HN_ + (c >> 2)];
    }
}

// ---------------------------------------------------------------------------
// xz precompute GEMM, 2-product (unchanged)
#define XST_BYTES 40960
#define XOFF_AL   16384
#define XOFF_BH   32768
#define SMEM_XZ   81920

__global__ __launch_bounds__(256) void xz_gemm() {
    extern __shared__ char smem[];
    const uint32_t sbase = smem_u32(smem);
    const int tid  = threadIdx.x;
    const int lane = tid & 31;
    const int wid  = tid >> 5;
    const int warp_m = wid >> 1;
    const int warp_n = wid & 1;

    const int z   = blockIdx.z;
    const int seq = z >> 8;
    const int t   = z & 255;
    const int inp = seq >> 1;
    const int b0  = blockIdx.y * 128;
    const int n0  = blockIdx.x * 64;

    auto load_chunk = [&](int k, int p) {
        const uint32_t st = sbase + (p ? XST_BYTES : 0);
        const int k0 = k * 64;
        #pragma unroll
        for (int j = 0; j < 4; j++) {
            int idx = tid + 256 * j;
            int row = idx >> 3;
            int seg = idx & 7;
            long base = ((long)(inp * BN_ + b0 + row) * TN_ + t) * XPAD + k0 + seg * 8;
            uint32_t dst = st + ((row * 8 + (seg ^ (row & 7))) << 4);
            cp16(dst,           g_xhi + base);
            cp16(dst + XOFF_AL, g_xlo + base);
        }
        #pragma unroll
        for (int j = 0; j < 2; j++) {
            int idx = tid + 256 * j;
            int row = idx >> 3;
            int seg = idx & 7;
            long base = ((long)seq * FOURH + n0 + row) * KPAD + k0 + seg * 8;
            uint32_t dst = st + XOFF_BH + ((row * 8 + (seg ^ (row & 7))) << 4);
            cp16(dst, g_whi + base);
        }
        CP_COMMIT();
    };

    float acc[2][4][4];
    uint32_t acch[2][4][2];
    #pragma unroll
    for (int mi = 0; mi < 2; mi++)
        #pragma unroll
        for (int ni = 0; ni < 4; ni++) {
            #pragma unroll
            for (int q = 0; q < 4; q++) acc[mi][ni][q] = 0.0f;
            acch[mi][ni][0] = 0u; acch[mi][ni][1] = 0u;
        }

    int arowb[2], arowx[2];
    #pragma unroll
    for (int mi = 0; mi < 2; mi++) {
        int r = warp_m * 32 + mi * 16 + (lane & 15);
        arowb[mi] = r * 128;
        arowx[mi] = r & 7;
    }
    int brow[2], browx[2];
    #pragma unroll
    for (int np = 0; np < 2; np++) {
        int n = warp_n * 32 + np * 16 + ((lane >> 4) << 3) + (lane & 7);
        brow[np]  = n * 128;
        browx[np] = n & 7;
    }
    const int asel = lane >> 4;
    const int bsel = (lane >> 3) & 1;

    load_chunk(0, 0);

    for (int k = 0; k < NCHX; k++) {
        const int p = k & 1;
        if (k + 1 < NCHX) load_chunk(k + 1, p ^ 1);
        if (k + 1 < NCHX) CP_WAIT(1); else CP_WAIT(0);
        __syncthreads();

        const uint32_t st = sbase + (p ? XST_BYTES : 0);
        #pragma unroll
        for (int kk = 0; kk < 4; kk++) {
            uint32_t ah[2][4], al[2][4];
            #pragma unroll
            for (int mi = 0; mi < 2; mi++) {
                int seg = 2 * kk + asel;
                uint32_t off = arowb[mi] + ((seg ^ arowx[mi]) << 4);
                LDSM_X4(ah[mi][0], ah[mi][1], ah[mi][2], ah[mi][3], st + off);
                LDSM_X4(al[mi][0], al[mi][1], al[mi][2], al[mi][3], st + XOFF_AL + off);
            }
            uint32_t bh[2][4];
            #pragma unroll
            for (int np = 0; np < 2; np++) {
                int seg = 2 * kk + bsel;
                uint32_t off = brow[np] + ((seg ^ browx[np]) << 4);
                LDSM_X4(bh[np][0], bh[np][1], bh[np][2], bh[np][3], st + XOFF_BH + off);
            }
            #pragma unroll
            for (int mi = 0; mi < 2; mi++)
                #pragma unroll
                for (int np = 0; np < 2; np++)
                    #pragma unroll
                    for (int h = 0; h < 2; h++) {
                        int ni = np * 2 + h;
                        uint32_t bhf[2] = { bh[np][2 * h], bh[np][2 * h + 1] };
                        MMA16816 (acc[mi][ni],  ah[mi], bhf);
                        MMA16816H(acch[mi][ni], al[mi], bhf);
                    }
        }
        __syncthreads();
    }

    float* xz = (seq < 2) ? g_xzA : g_xzB;
    const long zb = ((long)(seq & 1) * TN_ + t) * BN_;
    #pragma unroll
    for (int mi = 0; mi < 2; mi++) {
        #pragma unroll
        for (int ni = 0; ni < 4; ni++) {
            float2 c01 = __half22float2(*(__half2*)&acch[mi][ni][0]);
            float2 c23 = __half22float2(*(__half2*)&acch[mi][ni][1]);
            int col = n0 + warp_n * 32 + ni * 8 + 2 * (lane & 3);
            int r0  = b0 + warp_m * 32 + mi * 16 + (lane >> 2);
            float2 v01 = make_float2(acc[mi][ni][0] + c01.x, acc[mi][ni][1] + c01.y);
            float2 v23 = make_float2(acc[mi][ni][2] + c23.x, acc[mi][ni][3] + c23.y);
            *(float2*)&xz[(zb + r0)     * FOURH + col] = v01;
            *(float2*)&xz[(zb + r0 + 8) * FOURH + col] = v23;
        }
    }
}

// ---------------------------------------------------------------------------
// Per-step LSTM, 2-product MMA, 3-stage pipeline (ONE sync per chunk),
// register-prefetched state, store-only epilogue. 512 threads, 16 warps.
// SMEM: 3 stages (48KB each) @0/49152/98304; xz @147456 (64KB ends 212992);
//   bias @212992; len @213504. Total 214016. z buffer reuses [0, 64K).
#define ST_BYTES 49152
#define OFF_AL   16384
#define OFF_BH   32768
#define OFF_XZ   147456
#define OFF_BIAS 212992
#define OFF_LEN  213504
#define SMEM_TOTAL_STEP 214016

__global__ __launch_bounds__(512) void lstm_step_mma(const int* __restrict__ plen,
                                                     const int* __restrict__ hlen,
                                                     int s) {
    extern __shared__ char smem[];
    const uint32_t sbase = smem_u32(smem);
    const int tid  = threadIdx.x;
    const int lane = tid & 31;
    const int wid  = tid >> 5;
    const int warp_m = wid >> 2;
    const int warp_n = wid & 3;

    const int seq = blockIdx.z;
    const int rev = seq & 1;
    const int t   = rev ? (TN_ - 1 - s) : s;
    const int b0  = blockIdx.y * 128;
    const int n0  = blockIdx.x * 128;
    const int u0  = n0 >> 2;
    const int cur = s & 1;

    const int* __restrict__ len = (seq < 2) ? plen : hlen;
    if (tid < 128) {
        *(float*)(smem + OFF_BIAS + tid * 4) = g_bp[seq * FOURH + n0 + tid];
        *(int*)(smem + OFF_LEN + tid * 4) = len[b0 + tid];
    }

    const long hin_base  = ((long)cur * 4 + seq) * (BN_ * HN_);
    const long hout_base = ((long)(cur ^ 1) * 4 + seq) * (BN_ * HN_);
    const float* __restrict__ xzg = (seq < 2) ? g_xzA : g_xzB;
    const long zb = ((long)(seq & 1) * TN_ + t) * BN_;

    // ---- register-prefetch state (c, old h) for this thread's 8 elements --
    // Issued up front: 24 independent LDGs, hidden under the 8-chunk MMA loop.
    const float*  __restrict__ cg  = &g_c[0][0][0] + (long)seq * BN_ * HN_;
    const __half* __restrict__ hig = g_hhi + hin_base;
    const __half* __restrict__ lig = g_hlo + hin_base;
    float  c_old_r[8];
    __half hh_old_r[8], hl_old_r[8];
    long   ci_r[8];
    #pragma unroll
    for (int it = 0; it < 8; it++) {
        int e   = it * 512 + tid;
        int row = e >> 5;
        int u   = e & 31;
        long ci = (long)(b0 + row) * HN_ + u0 + u;
        ci_r[it]     = ci;
        c_old_r[it]  = __ldg(cg + ci);
        hh_old_r[it] = __ldg(hig + ci);
        hl_old_r[it] = __ldg(lig + ci);
    }

    auto load_chunk = [&](int k, int stg) {
        const uint32_t st = sbase + stg * ST_BYTES;
        const int k0 = k * 64;
        #pragma unroll
        for (int j = 0; j < 2; j++) {           // A = h: hi + lo
            int idx = tid + 512 * j;
            int row = idx >> 3;
            int seg = idx & 7;
            long base = hin_base + (long)(b0 + row) * HN_ + k0 + seg * 8;
            uint32_t dst = st + ((row * 8 + (seg ^ (row & 7))) << 4);
            cp16(dst,          g_hhi + base);
            cp16(dst + OFF_AL, g_hlo + base);
        }
        #pragma unroll
        for (int j = 0; j < 2; j++) {           // B = Wh region: hi only
            int idx = tid + 512 * j;
            int row = idx >> 3;
            int seg = idx & 7;
            long base = ((long)seq * FOURH + n0 + row) * KPAD + XPAD + k0 + seg * 8;
            uint32_t dst = st + OFF_BH + ((row * 8 + (seg ^ (row & 7))) << 4);
            cp16(dst, g_whi + base);
        }
        // xz piece k: 16 rows x 128 cols fp32 (1 seg/thread)
        {
            int row = (k << 4) + (tid >> 5);
            int seg = tid & 31;
            const float* src = xzg + (zb + b0 + row) * FOURH + n0 + seg * 4;
            cp16(sbase + OFF_XZ + row * 512 + seg * 16, src);
        }
        CP_COMMIT();
    };

    float acc[2][4][4];
    uint32_t acch[2][4][2];
    #pragma unroll
    for (int mi = 0; mi < 2; mi++)
        #pragma unroll
        for (int ni = 0; ni < 4; ni++) {
            #pragma unroll
            for (int q = 0; q < 4; q++) acc[mi][ni][q] = 0.0f;
            acch[mi][ni][0] = 0u; acch[mi][ni][1] = 0u;
        }

    int arowb[2], arowx[2];
    #pragma unroll
    for (int mi = 0; mi < 2; mi++) {
        int r = warp_m * 32 + mi * 16 + (lane & 15);
        arowb[mi] = r * 128;
        arowx[mi] = r & 7;
    }
    int brow[2], browx[2];
    #pragma unroll
    for (int np = 0; np < 2; np++) {
        int n = warp_n * 32 + np * 16 + ((lane >> 4) << 3) + (lane & 7);
        brow[np]  = n * 128;
        browx[np] = n & 7;
    }
    const int asel = lane >> 4;
    const int bsel = (lane >> 3) & 1;

    load_chunk(0, 0);
    load_chunk(1, 1);

    for (int k = 0; k < NCHS; k++) {
        if (k + 1 < NCHS) { CP_WAIT(1); } else { CP_WAIT(0); }
        __syncthreads();
        if (k + 2 < NCHS) load_chunk(k + 2, (k + 2) % 3);

        const uint32_t st = sbase + (k % 3) * ST_BYTES;
        #pragma unroll
        for (int kk = 0; kk < 4; kk++) {
            uint32_t ah[2][4], al[2][4];
            #pragma unroll
            for (int mi = 0; mi < 2; mi++) {
                int seg = 2 * kk + asel;
                uint32_t off = arowb[mi] + ((seg ^ arowx[mi]) << 4);
                LDSM_X4(ah[mi][0], ah[mi][1], ah[mi][2], ah[mi][3], st + off);
                LDSM_X4(al[mi][0], al[mi][1], al[mi][2], al[mi][3], st + OFF_AL + off);
            }
            uint32_t bh[2][4];
            #pragma unroll
            for (int np = 0; np < 2; np++) {
                int seg = 2 * kk + bsel;
                uint32_t off = brow[np] + ((seg ^ browx[np]) << 4);
                LDSM_X4(bh[np][0], bh[np][1], bh[np][2], bh[np][3], st + OFF_BH + off);
            }
            #pragma unroll
            for (int mi = 0; mi < 2; mi++)
                #pragma unroll
                for (int np = 0; np < 2; np++)
                    #pragma unroll
                    for (int h = 0; h < 2; h++) {
                        int ni = np * 2 + h;
                        uint32_t bhf[2] = { bh[np][2 * h], bh[np][2 * h + 1] };
                        MMA16816 (acc[mi][ni],  ah[mi], bhf);
                        MMA16816H(acch[mi][ni], al[mi], bhf);
                    }
        }
    }
    __syncthreads();   // all warps done reading stages before z-buffer reuse

    // ---- phase 1: fragments -> swizzled z buffer [0, 64K) -----------------
    #pragma unroll
    for (int mi = 0; mi < 2; mi++) {
        #pragma unroll
        for (int ni = 0; ni < 4; ni++) {
            float2 c01 = __half22float2(*(__half2*)&acch[mi][ni][0]);
            float2 c23 = __half22float2(*(__half2*)&acch[mi][ni][1]);
            int col = warp_n * 32 + ni * 8 + 2 * (lane & 3);
            int rl0 = warp_m * 32 + mi * 16 + (lane >> 2);
            float2 v01 = make_float2(acc[mi][ni][0] + c01.x, acc[mi][ni][1] + c01.y);
            float2 v23 = make_float2(acc[mi][ni][2] + c23.x, acc[mi][ni][3] + c23.y);
            int g  = col >> 2;
            int ob = (col & 3) * 4;
            *(float2*)(smem + rl0 * 512 + (((g ^ (rl0 & 7)) << 4) | ob)) = v01;
            int rl1 = rl0 + 8;
            *(float2*)(smem + rl1 * 512 + (((g ^ (rl1 & 7)) << 4) | ob)) = v23;
        }
    }
    __syncthreads();

    // ---- phase 2: all 512 threads, 8 elements; registers in, stores out ---
    const float* bias_s = (const float*)(smem + OFF_BIAS);
    const int*   len_s  = (const int*)(smem + OFF_LEN);
    float*  cgw  = &g_c[0][0][0] + (long)seq * BN_ * HN_;
    __half* hog  = g_hhi + hout_base;
    __half* log_ = g_hlo + hout_base;

    #pragma unroll
    for (int it = 0; it < 8; it++) {
        int e   = it * 512 + tid;
        int row = e >> 5;
        int u   = e & 31;
        float4 zv = *(const float4*)(smem + row * 512 + ((u ^ (row & 7)) << 4));
        float4 xv = *(const float4*)(smem + OFF_XZ + row * 512 + u * 16);
        float4 bv = *(const float4*)(bias_s + 4 * u);
        float iv = zv.x + xv.x + bv.x;
        float jv = zv.y + xv.y + bv.y;
        float fv = zv.z + xv.z + bv.z;
        float ov = zv.w + xv.w + bv.w;
        bool  m  = (t < len_s[row]);
        float c_old = c_old_r[it];
        float nc = c_old * sig_(fv + 1.0f) + sig_(iv) * tanh_(jv);
        float nh = tanh_(nc) * sig_(ov);
        cgw[ci_r[it]] = m ? nc : c_old;
        __half hh, hl;
        if (m) {
            hh = __float2half(nh);
            hl = __float2half(nh - __half2float(hh));
        } else {
            hh = hh_old_r[it];
            hl = hl_old_r[it];
        }
        hog[ci_r[it]]  = hh;
        log_[ci_r[it]] = hl;
    }
}

// ---------------------------------------------------------------------------
// MLP head (fp32)
__global__ void gather_x_kernel() {
    int i = blockIdx.x * blockDim.x + threadIdx.x;
    if (i >= BN_ * FOURH) return;
    int b   = i >> 11;
    int col = i & 2047;
    g_x[i] = g_c[col >> 9][b][col & 511];
}

#define BMT 64
#define BUT 64
#define KT  16
__global__ __launch_bounds__(256) void mlp_gemm_kernel(const float* __restrict__ W,
                                                       const float* __restrict__ bias,
                                                       int layer) {
    const float* A; float* C; int K, N;
    if (layer == 1)      { A = g_x;  C = g_m1; K = 2048; N = 1024; }
    else if (layer == 2) { A = g_m1; C = g_m2; K = 1024; N = 1024; }
    else                 { A = g_m2; C = g_m3; K = 1024; N = 1024; }

    const int m0 = blockIdx.y * BMT;
    const int n0 = blockIdx.x * BUT;
    __shared__ float As[KT][BMT];
    __shared__ float Bs[KT][BUT];
    const int tid = threadIdx.x;
    const int r0  = (tid >> 4) * 4;
    const int nt0 = (tid & 15) * 4;

    float acc[4][4];
    #pragma unroll
    for (int r = 0; r < 4; r++)
        #pragma unroll
        for (int u = 0; u < 4; u++) acc[r][u] = 0.0f;

    for (int k0 = 0; k0 < K; k0 += KT) {
        {
            int r  = tid >> 2;
            int kq = (tid & 3) * 4;
            #pragma unroll
            for (int i = 0; i < 4; i++)
                As[kq + i][r] = A[(m0 + r) * K + k0 + kq + i];
        }
        {
            int kk = tid >> 4;
            int uu = (tid & 15) * 4;
            *(float4*)&Bs[kk][uu] = *(const float4*)(W + (k0 + kk) * N + n0 + uu);
        }
        __syncthreads();
        #pragma unroll
        for (int kk = 0; kk < KT; kk++) {
            float4 a4 = *(const float4*)&As[kk][r0];
            float4 b4 = *(const float4*)&Bs[kk][nt0];
            float av[4] = {a4.x, a4.y, a4.z, a4.w};
            float bv[4] = {b4.x, b4.y, b4.z, b4.w};
            #pragma unroll
            for (int r = 0; r < 4; r++)
                #pragma unroll
                for (int u = 0; u < 4; u++)
                    acc[r][u] = fmaf(av[r], bv[u], acc[r][u]);
        }
        __syncthreads();
    }
    #pragma unroll
    for (int r = 0; r < 4; r++)
        #pragma unroll
        for (int u = 0; u < 4; u++) {
            int n = n0 + nt0 + u;
            C[(m0 + r0 + r) * N + n] = tanhf(acc[r][u] + bias[n]);
        }
}

__global__ void final_logits_kernel(const float* __restrict__ W4,
                                    const float* __restrict__ b4,
                                    float* __restrict__ out) {
    int b    = blockIdx.x;
    int w    = threadIdx.x >> 5;
    int lane = threadIdx.x & 31;
    if (w >= 3) return;
    float sum = 0.0f;
    for (int k = lane; k < 1024; k += 32)
        sum += g_m3[b * 1024 + k] * W4[k * 3 + w];
    #pragma unroll
    for (int off = 16; off; off >>= 1)
        sum += __shfl_down_sync(0xffffffff, sum, off);
    if (lane == 0) out[b * 3 + w] = sum + b4[w];
}

// ---------------------------------------------------------------------------
extern "C" void kernel_launch(void* const* d_in, const int* in_sizes, int n_in,
                              void* d_out, int out_size) {
    const float* premises   = (const float*)d_in[0];
    const float* hypotheses = (const float*)d_in[1];
    const int*   plen       = (const int*)d_in[2];
    const int*   hlen       = (const int*)d_in[3];

    WPtrs wp;
    for (int i = 0; i < 4; i++) {
        wp.wx[i]   = (const float*)d_in[4 + 3 * i + 0];
        wp.wh[i]   = (const float*)d_in[4 + 3 * i + 1];
        wp.bias[i] = (const float*)d_in[4 + 3 * i + 2];
    }
    const float* W1 = (const float*)d_in[16];
    const float* b1 = (const float*)d_in[17];
    const float* W2 = (const float*)d_in[18];
    const float* b2 = (const float*)d_in[19];
    const float* W3 = (const float*)d_in[20];
    const float* b3 = (const float*)d_in[21];
    const float* W4 = (const float*)d_in[22];
    const float* b4 = (const float*)d_in[23];
    float* out = (float*)d_out;

    cudaFuncSetAttribute(lstm_step_mma, cudaFuncAttributeMaxDynamicSharedMemorySize,
                         SMEM_TOTAL_STEP);
    cudaFuncSetAttribute(xz_gemm, cudaFuncAttributeMaxDynamicSharedMemorySize,
                         SMEM_XZ);

    {
        long long n = NTOT_;
        preproc_all<<<(unsigned)((n + 255) / 256), 256>>>(premises, hypotheses, wp);
    }

    xz_gemm<<<dim3(32, 2, 4 * TN_), 256, SMEM_XZ>>>();

    dim3 grid(16, 2, 4);
    for (int s = 0; s < TN_; s++)
        lstm_step_mma<<<grid, 512, SMEM_TOTAL_STEP>>>(plen, hlen, s);

    gather_x_kernel<<<(BN_ * FOURH + 255) / 256, 256>>>();
    mlp_gemm_kernel<<<dim3(1024 / BUT, BN_ / BMT), 256>>>(W1, b1, 1);
    mlp_gemm_kernel<<<dim3(1024 / BUT, BN_ / BMT), 256>>>(W2, b2, 2);
    mlp_gemm_kernel<<<dim3(1024 / BUT, BN_ / BMT), 256>>>(W3, b3, 3);
    final_logits_kernel<<<BN_, 96>>>(W4, b4, out);
}

// round 16
// speedup vs baseline: 1.0590x; 1.0247x over previous
#include <cuda_runtime.h>
#include <cuda_fp16.h>
#include <math.h>
#include <stdint.h>

// ---------------------------------------------------------------------------
// Problem constants
#define BN_   256
#define TN_   256
#define DN_   300
#define HN_   512
#define XPAD  320
#define KPAD  832
#define NCHX  5
#define NCHS  8
#define FOURH 2048

// ---------------------------------------------------------------------------
// Scratch (device globals)
__device__ __half g_xhi[2ll * BN_ * TN_ * XPAD];
__device__ __half g_xlo[2ll * BN_ * TN_ * XPAD];
__device__ __half g_whi[4ll * FOURH * KPAD];
__device__ float  g_bp [4 * FOURH];
__device__ __half g_hhi[2ll * 4 * BN_ * HN_];
__device__ __half g_hlo[2ll * 4 * BN_ * HN_];
__device__ float  g_c  [4][BN_][HN_];
__device__ float  g_x  [BN_ * FOURH];
__device__ float  g_m1[BN_ * 1024];
__device__ float  g_m2[BN_ * 1024];
__device__ float  g_m3[BN_ * 1024];

#define XZ_PER (2ll * TN_ * BN_ * FOURH)
__device__ float g_xzA[XZ_PER];
__device__ float g_xzB[XZ_PER];

__device__ __forceinline__ float sig_(float x) {
    return __fdividef(1.0f, 1.0f + __expf(-x));
}
__device__ __forceinline__ float tanh_(float x) {
    float ax = fabsf(x);
    float e  = __expf(-2.0f * ax);
    float r  = __fdividef(1.0f - e, 1.0f + e);
    return copysignf(r, x);
}

__device__ __forceinline__ uint32_t smem_u32(const void* p) {
    uint32_t a;
    asm("{ .reg .u64 t; cvta.to.shared.u64 t, %1; cvt.u32.u64 %0, t; }" : "=r"(a) : "l"(p));
    return a;
}
__device__ __forceinline__ void cp16(uint32_t dst, const void* src) {
    asm volatile("cp.async.cg.shared.global [%0], [%1], 16;" :: "r"(dst), "l"(src));
}
#define CP_COMMIT() asm volatile("cp.async.commit_group;" ::: "memory")
#define CP_WAIT(N)  asm volatile("cp.async.wait_group %0;" :: "n"(N) : "memory")

#define LDSM_X4(r0, r1, r2, r3, addr)                                         \
    asm volatile("ldmatrix.sync.aligned.m8n8.x4.shared.b16 {%0,%1,%2,%3}, [%4];" \
        : "=r"(r0), "=r"(r1), "=r"(r2), "=r"(r3) : "r"(addr))

#define MMA16816(d, a, b)                                                     \
    asm volatile("mma.sync.aligned.m16n8k16.row.col.f32.f16.f16.f32 "         \
        "{%0,%1,%2,%3}, {%4,%5,%6,%7}, {%8,%9}, {%0,%1,%2,%3};"               \
        : "+f"((d)[0]), "+f"((d)[1]), "+f"((d)[2]), "+f"((d)[3])              \
        : "r"((a)[0]), "r"((a)[1]), "r"((a)[2]), "r"((a)[3]),                 \
          "r"((b)[0]), "r"((b)[1]))

#define MMA16816H(d, a, b)                                                    \
    asm volatile("mma.sync.aligned.m16n8k16.row.col.f16.f16.f16.f16 "         \
        "{%0,%1}, {%2,%3,%4,%5}, {%6,%7}, {%0,%1};"                           \
        : "+r"((d)[0]), "+r"((d)[1])                                          \
        : "r"((a)[0]), "r"((a)[1]), "r"((a)[2]), "r"((a)[3]),                 \
          "r"((b)[0]), "r"((b)[1]))

// ---------------------------------------------------------------------------
struct WPtrs { const float* wx[4]; const float* wh[4]; const float* bias[4]; };

#define NXE_ (2ll * BN_ * TN_ * XPAD)
#define NWE_ (4ll * FOURH * KPAD)
#define NHE_ (2ll * 4 * BN_ * HN_)
#define NCE_ (4ll * BN_ * HN_)
#define NBE_ (4ll * FOURH)
#define NTOT_ (NXE_ + NWE_ + NHE_ + NCE_ + NBE_)

__global__ void preproc_all(const float* __restrict__ prem, const float* __restrict__ hyp,
                            WPtrs wp) {
    long long i = (long long)blockIdx.x * blockDim.x + threadIdx.x;
    if (i < NXE_) {
        int k = (int)(i % XPAD);
        long long r = i / XPAD;
        int t = (int)(r % TN_); r /= TN_;
        int b = (int)(r % BN_);
        int inp = (int)(r / BN_);
        float v = 0.0f;
        if (k < DN_) {
            const float* src = inp ? hyp : prem;
            v = src[((long long)b * TN_ + t) * DN_ + k];
        }
        __half h = __float2half(v);
        g_xhi[i] = h;
        g_xlo[i] = __float2half(v - __half2float(h));
        return;
    }
    i -= NXE_;
    if (i < NWE_) {
        int kp = (int)(i % KPAD);
        long long r = i / KPAD;
        int c   = (int)(r % FOURH);
        int seq = (int)(r / FOURH);
        int oc  = (c & 3) * HN_ + (c >> 2);
        float v = 0.0f;
        if (kp < DN_)        v = wp.wx[seq][(long long)kp * FOURH + oc];
        else if (kp >= XPAD) v = wp.wh[seq][(long long)(kp - XPAD) * FOURH + oc];
        g_whi[i] = __float2half(v);
        return;
    }
    i -= NWE_;
    if (i < NHE_) {
        g_hhi[i] = __float2half(0.f);
        g_hlo[i] = __float2half(0.f);
        return;
    }
    i -= NHE_;
    if (i < NCE_) {
        (&g_c[0][0][0])[i] = 0.0f;
        return;
    }
    i -= NCE_;
    if (i < NBE_) {
        int c = (int)(i & (FOURH - 1));
        int seq = (int)(i >> 11);
        g_bp[i] = wp.bias[seq][(c & 3) * HN_ + (c >> 2)];
    }
}

// ---------------------------------------------------------------------------
// xz precompute GEMM, 2-product (unchanged)
#define XST_BYTES 40960
#define XOFF_AL   16384
#define XOFF_BH   32768
#define SMEM_XZ   81920

__global__ __launch_bounds__(256) void xz_gemm() {
    extern __shared__ char smem[];
    const uint32_t sbase = smem_u32(smem);
    const int tid  = threadIdx.x;
    const int lane = tid & 31;
    const int wid  = tid >> 5;
    const int warp_m = wid >> 1;
    const int warp_n = wid & 1;

    const int z   = blockIdx.z;
    const int seq = z >> 8;
    const int t   = z & 255;
    const int inp = seq >> 1;
    const int b0  = blockIdx.y * 128;
    const int n0  = blockIdx.x * 64;

    auto load_chunk = [&](int k, int p) {
        const uint32_t st = sbase + (p ? XST_BYTES : 0);
        const int k0 = k * 64;
        #pragma unroll
        for (int j = 0; j < 4; j++) {
            int idx = tid + 256 * j;
            int row = idx >> 3;
            int seg = idx & 7;
            long base = ((long)(inp * BN_ + b0 + row) * TN_ + t) * XPAD + k0 + seg * 8;
            uint32_t dst = st + ((row * 8 + (seg ^ (row & 7))) << 4);
            cp16(dst,           g_xhi + base);
            cp16(dst + XOFF_AL, g_xlo + base);
        }
        #pragma unroll
        for (int j = 0; j < 2; j++) {
            int idx = tid + 256 * j;
            int row = idx >> 3;
            int seg = idx & 7;
            long base = ((long)seq * FOURH + n0 + row) * KPAD + k0 + seg * 8;
            uint32_t dst = st + XOFF_BH + ((row * 8 + (seg ^ (row & 7))) << 4);
            cp16(dst, g_whi + base);
        }
        CP_COMMIT();
    };

    float acc[2][4][4];
    uint32_t acch[2][4][2];
    #pragma unroll
    for (int mi = 0; mi < 2; mi++)
        #pragma unroll
        for (int ni = 0; ni < 4; ni++) {
            #pragma unroll
            for (int q = 0; q < 4; q++) acc[mi][ni][q] = 0.0f;
            acch[mi][ni][0] = 0u; acch[mi][ni][1] = 0u;
        }

    int arowb[2], arowx[2];
    #pragma unroll
    for (int mi = 0; mi < 2; mi++) {
        int r = warp_m * 32 + mi * 16 + (lane & 15);
        arowb[mi] = r * 128;
        arowx[mi] = r & 7;
    }
    int brow[2], browx[2];
    #pragma unroll
    for (int np = 0; np < 2; np++) {
        int n = warp_n * 32 + np * 16 + ((lane >> 4) << 3) + (lane & 7);
        brow[np]  = n * 128;
        browx[np] = n & 7;
    }
    const int asel = lane >> 4;
    const int bsel = (lane >> 3) & 1;

    load_chunk(0, 0);

    for (int k = 0; k < NCHX; k++) {
        const int p = k & 1;
        if (k + 1 < NCHX) load_chunk(k + 1, p ^ 1);
        if (k + 1 < NCHX) CP_WAIT(1); else CP_WAIT(0);
        __syncthreads();

        const uint32_t st = sbase + (p ? XST_BYTES : 0);
        #pragma unroll
        for (int kk = 0; kk < 4; kk++) {
            uint32_t ah[2][4], al[2][4];
            #pragma unroll
            for (int mi = 0; mi < 2; mi++) {
                int seg = 2 * kk + asel;
                uint32_t off = arowb[mi] + ((seg ^ arowx[mi]) << 4);
                LDSM_X4(ah[mi][0], ah[mi][1], ah[mi][2], ah[mi][3], st + off);
                LDSM_X4(al[mi][0], al[mi][1], al[mi][2], al[mi][3], st + XOFF_AL + off);
            }
            uint32_t bh[2][4];
            #pragma unroll
            for (int np = 0; np < 2; np++) {
                int seg = 2 * kk + bsel;
                uint32_t off = brow[np] + ((seg ^ browx[np]) << 4);
                LDSM_X4(bh[np][0], bh[np][1], bh[np][2], bh[np][3], st + XOFF_BH + off);
            }
            #pragma unroll
            for (int mi = 0; mi < 2; mi++)
                #pragma unroll
                for (int np = 0; np < 2; np++)
                    #pragma unroll
                    for (int h = 0; h < 2; h++) {
                        int ni = np * 2 + h;
                        uint32_t bhf[2] = { bh[np][2 * h], bh[np][2 * h + 1] };
                        MMA16816 (acc[mi][ni],  ah[mi], bhf);
                        MMA16816H(acch[mi][ni], al[mi], bhf);
                    }
        }
        __syncthreads();
    }

    float* xz = (seq < 2) ? g_xzA : g_xzB;
    const long zb = ((long)(seq & 1) * TN_ + t) * BN_;
    #pragma unroll
    for (int mi = 0; mi < 2; mi++) {
        #pragma unroll
        for (int ni = 0; ni < 4; ni++) {
            float2 c01 = __half22float2(*(__half2*)&acch[mi][ni][0]);
            float2 c23 = __half22float2(*(__half2*)&acch[mi][ni][1]);
            int col = n0 + warp_n * 32 + ni * 8 + 2 * (lane & 3);
            int r0  = b0 + warp_m * 32 + mi * 16 + (lane >> 2);
            float2 v01 = make_float2(acc[mi][ni][0] + c01.x, acc[mi][ni][1] + c01.y);
            float2 v23 = make_float2(acc[mi][ni][2] + c23.x, acc[mi][ni][3] + c23.y);
            *(float2*)&xz[(zb + r0)     * FOURH + col] = v01;
            *(float2*)&xz[(zb + r0 + 8) * FOURH + col] = v23;
        }
    }
}

// ---------------------------------------------------------------------------
// Per-step LSTM, 2-product MMA (R12 structure: 2-stage, load-before-wait),
// SMEM-staged inputs, direct-global-store epilogue. 512 threads, 16 warps.
// SMEM: stage = Ah(16K)|Al(16K)|Bh(16K) = 48KB, 2 stages @0/@49152.
//   xz @98304 (64KB), c @163840 (16KB), hh @180224 (8KB), hl @188416 (8KB),
//   bias @196608, len @197120. Total 197632.
// z buffer (phase1) reuses [0, 65536).
#define ST_BYTES 49152
#define OFF_AL   16384
#define OFF_BH   32768
#define OFF_XZ   98304
#define OFF_C    163840
#define OFF_HH   180224
#define OFF_HL   188416
#define OFF_BIAS 196608
#define OFF_LEN  197120
#define SMEM_TOTAL_STEP 197632

__global__ __launch_bounds__(512) void lstm_step_mma(const int* __restrict__ plen,
                                                     const int* __restrict__ hlen,
                                                     int s) {
    extern __shared__ char smem[];
    const uint32_t sbase = smem_u32(smem);
    const int tid  = threadIdx.x;
    const int lane = tid & 31;
    const int wid  = tid >> 5;
    const int warp_m = wid >> 2;
    const int warp_n = wid & 3;

    const int seq = blockIdx.z;
    const int rev = seq & 1;
    const int t   = rev ? (TN_ - 1 - s) : s;
    const int b0  = blockIdx.y * 128;
    const int n0  = blockIdx.x * 128;
    const int u0  = n0 >> 2;
    const int cur = s & 1;

    const int* __restrict__ len = (seq < 2) ? plen : hlen;
    if (tid < 128) {
        *(float*)(smem + OFF_BIAS + tid * 4) = g_bp[seq * FOURH + n0 + tid];
        *(int*)(smem + OFF_LEN + tid * 4) = len[b0 + tid];
    }

    const long hin_base  = ((long)cur * 4 + seq) * (BN_ * HN_);
    const long hout_base = ((long)(cur ^ 1) * 4 + seq) * (BN_ * HN_);
    const float* __restrict__ xzg = (seq < 2) ? g_xzA : g_xzB;
    const long zb = ((long)(seq & 1) * TN_ + t) * BN_;

    auto load_chunk = [&](int k, int p) {
        const uint32_t st = sbase + (p ? ST_BYTES : 0);
        const int k0 = k * 64;
        #pragma unroll
        for (int j = 0; j < 2; j++) {           // A = h: hi + lo
            int idx = tid + 512 * j;
            int row = idx >> 3;
            int seg = idx & 7;
            long base = hin_base + (long)(b0 + row) * HN_ + k0 + seg * 8;
            uint32_t dst = st + ((row * 8 + (seg ^ (row & 7))) << 4);
            cp16(dst,          g_hhi + base);
            cp16(dst + OFF_AL, g_hlo + base);
        }
        #pragma unroll
        for (int j = 0; j < 2; j++) {           // B = Wh region: hi only
            int idx = tid + 512 * j;
            int row = idx >> 3;
            int seg = idx & 7;
            long base = ((long)seq * FOURH + n0 + row) * KPAD + XPAD + k0 + seg * 8;
            uint32_t dst = st + OFF_BH + ((row * 8 + (seg ^ (row & 7))) << 4);
            cp16(dst, g_whi + base);
        }
        // xz piece k: 16 rows x 128 cols fp32
        {
            int row = (k << 4) + (tid >> 5);
            int seg = tid & 31;
            const float* src = xzg + (zb + b0 + row) * FOURH + n0 + seg * 4;
            cp16(sbase + OFF_XZ + row * 512 + seg * 16, src);
        }
        // c piece k (threads 0..127); old-h pieces (threads 128..255)
        if (tid < 128) {
            int row = (k << 4) + (tid >> 3);
            int seg = tid & 7;
            cp16(sbase + OFF_C + row * 128 + seg * 16, &g_c[seq][b0 + row][u0 + seg * 4]);
        } else if (tid < 192) {
            int i2  = tid - 128;
            int row = (k << 4) + (i2 >> 2);
            int sg  = i2 & 3;
            cp16(sbase + OFF_HH + row * 64 + sg * 16,
                 g_hhi + hin_base + (long)(b0 + row) * HN_ + u0 + sg * 8);
        } else if (tid < 256) {
            int i2  = tid - 192;
            int row = (k << 4) + (i2 >> 2);
            int sg  = i2 & 3;
            cp16(sbase + OFF_HL + row * 64 + sg * 16,
                 g_hlo + hin_base + (long)(b0 + row) * HN_ + u0 + sg * 8);
        }
        CP_COMMIT();
    };

    float acc[2][4][4];
    uint32_t acch[2][4][2];
    #pragma unroll
    for (int mi = 0; mi < 2; mi++)
        #pragma unroll
        for (int ni = 0; ni < 4; ni++) {
            #pragma unroll
            for (int q = 0; q < 4; q++) acc[mi][ni][q] = 0.0f;
            acch[mi][ni][0] = 0u; acch[mi][ni][1] = 0u;
        }

    int arowb[2], arowx[2];
    #pragma unroll
    for (int mi = 0; mi < 2; mi++) {
        int r = warp_m * 32 + mi * 16 + (lane & 15);
        arowb[mi] = r * 128;
        arowx[mi] = r & 7;
    }
    int brow[2], browx[2];
    #pragma unroll
    for (int np = 0; np < 2; np++) {
        int n = warp_n * 32 + np * 16 + ((lane >> 4) << 3) + (lane & 7);
        brow[np]  = n * 128;
        browx[np] = n & 7;
    }
    const int asel = lane >> 4;
    const int bsel = (lane >> 3) & 1;

    load_chunk(0, 0);

    for (int k = 0; k < NCHS; k++) {
        const int p = k & 1;
        if (k + 1 < NCHS) load_chunk(k + 1, p ^ 1);
        if (k + 1 < NCHS) CP_WAIT(1); else CP_WAIT(0);
        __syncthreads();

        const uint32_t st = sbase + (p ? ST_BYTES : 0);
        #pragma unroll
        for (int kk = 0; kk < 4; kk++) {
            uint32_t ah[2][4], al[2][4];
            #pragma unroll
            for (int mi = 0; mi < 2; mi++) {
                int seg = 2 * kk + asel;
                uint32_t off = arowb[mi] + ((seg ^ arowx[mi]) << 4);
                LDSM_X4(ah[mi][0], ah[mi][1], ah[mi][2], ah[mi][3], st + off);
                LDSM_X4(al[mi][0], al[mi][1], al[mi][2], al[mi][3], st + OFF_AL + off);
            }
            uint32_t bh[2][4];
            #pragma unroll
            for (int np = 0; np < 2; np++) {
                int seg = 2 * kk + bsel;
                uint32_t off = brow[np] + ((seg ^ browx[np]) << 4);
                LDSM_X4(bh[np][0], bh[np][1], bh[np][2], bh[np][3], st + OFF_BH + off);
            }
            #pragma unroll
            for (int mi = 0; mi < 2; mi++)
                #pragma unroll
                for (int np = 0; np < 2; np++)
                    #pragma unroll
                    for (int h = 0; h < 2; h++) {
                        int ni = np * 2 + h;
                        uint32_t bhf[2] = { bh[np][2 * h], bh[np][2 * h + 1] };
                        MMA16816 (acc[mi][ni],  ah[mi], bhf);
                        MMA16816H(acch[mi][ni], al[mi], bhf);
                    }
        }
        __syncthreads();
    }

    // ---- phase 1: fragments -> swizzled z buffer [0, 64K) -----------------
    #pragma unroll
    for (int mi = 0; mi < 2; mi++) {
        #pragma unroll
        for (int ni = 0; ni < 4; ni++) {
            float2 c01 = __half22float2(*(__half2*)&acch[mi][ni][0]);
            float2 c23 = __half22float2(*(__half2*)&acch[mi][ni][1]);
            int col = warp_n * 32 + ni * 8 + 2 * (lane & 3);
            int rl0 = warp_m * 32 + mi * 16 + (lane >> 2);
            float2 v01 = make_float2(acc[mi][ni][0] + c01.x, acc[mi][ni][1] + c01.y);
            float2 v23 = make_float2(acc[mi][ni][2] + c23.x, acc[mi][ni][3] + c23.y);
            int g  = col >> 2;
            int ob = (col & 3) * 4;
            *(float2*)(smem + rl0 * 512 + (((g ^ (rl0 & 7)) << 4) | ob)) = v01;
            int rl1 = rl0 + 8;
            *(float2*)(smem + rl1 * 512 + (((g ^ (rl1 & 7)) << 4) | ob)) = v23;
        }
    }
    __syncthreads();

    // ---- phase 2: all 512 threads, 8 elements; SMEM in, global stores out --
    const float* bias_s = (const float*)(smem + OFF_BIAS);
    const int*   len_s  = (const int*)(smem + OFF_LEN);
    const float* c_s    = (const float*)(smem + OFF_C);
    const __half* hh_s  = (const __half*)(smem + OFF_HH);
    const __half* hl_s  = (const __half*)(smem + OFF_HL);
    float*  cgw  = &g_c[0][0][0] + (long)seq * BN_ * HN_;
    __half* hog  = g_hhi + hout_base;
    __half* log_ = g_hlo + hout_base;

    #pragma unroll
    for (int it = 0; it < 8; it++) {
        int e   = it * 512 + tid;
        int row = e >> 5;
        int u   = e & 31;
        float4 zv = *(const float4*)(smem + row * 512 + ((u ^ (row & 7)) << 4));
        float4 xv = *(const float4*)(smem + OFF_XZ + row * 512 + u * 16);
        float4 bv = *(const float4*)(bias_s + 4 * u);
        float iv = zv.x + xv.x + bv.x;
        float jv = zv.y + xv.y + bv.y;
        float fv = zv.z + xv.z + bv.z;
        float ov = zv.w + xv.w + bv.w;
        bool  m  = (t < len_s[row]);
        float c_old = c_s[row * 32 + u];
        float nc = c_old * sig_(fv + 1.0f) + sig_(iv) * tanh_(jv);
        float nh = tanh_(nc) * sig_(ov);
        long  ci = (long)(b0 + row) * HN_ + u0 + u;
        cgw[ci] = m ? nc : c_old;
        __half hh, hl;
        if (m) {
            hh = __float2half(nh);
            hl = __float2half(nh - __half2float(hh));
        } else {
            hh = hh_s[row * 32 + u];
            hl = hl_s[row * 32 + u];
        }
        hog[ci]  = hh;
        log_[ci] = hl;
    }
}

// ---------------------------------------------------------------------------
// MLP head (fp32)
__global__ void gather_x_kernel() {
    int i = blockIdx.x * blockDim.x + threadIdx.x;
    if (i >= BN_ * FOURH) return;
    int b   = i >> 11;
    int col = i & 2047;
    g_x[i] = g_c[col >> 9][b][col & 511];
}

#define BMT 64
#define BUT 64
#define KT  16
__global__ __launch_bounds__(256) void mlp_gemm_kernel(const float* __restrict__ W,
                                                       const float* __restrict__ bias,
                                                       int layer) {
    const float* A; float* C; int K, N;
    if (layer == 1)      { A = g_x;  C = g_m1; K = 2048; N = 1024; }
    else if (layer == 2) { A = g_m1; C = g_m2; K = 1024; N = 1024; }
    else                 { A = g_m2; C = g_m3; K = 1024; N = 1024; }

    const int m0 = blockIdx.y * BMT;
    const int n0 = blockIdx.x * BUT;
    __shared__ float As[KT][BMT];
    __shared__ float Bs[KT][BUT];
    const int tid = threadIdx.x;
    const int r0  = (tid >> 4) * 4;
    const int nt0 = (tid & 15) * 4;

    float acc[4][4];
    #pragma unroll
    for (int r = 0; r < 4; r++)
        #pragma unroll
        for (int u = 0; u < 4; u++) acc[r][u] = 0.0f;

    for (int k0 = 0; k0 < K; k0 += KT) {
        {
            int r  = tid >> 2;
            int kq = (tid & 3) * 4;
            #pragma unroll
            for (int i = 0; i < 4; i++)
                As[kq + i][r] = A[(m0 + r) * K + k0 + kq + i];
        }
        {
            int kk = tid >> 4;
            int uu = (tid & 15) * 4;
            *(float4*)&Bs[kk][uu] = *(const float4*)(W + (k0 + kk) * N + n0 + uu);
        }
        __syncthreads();
        #pragma unroll
        for (int kk = 0; kk < KT; kk++) {
            float4 a4 = *(const float4*)&As[kk][r0];
            float4 b4 = *(const float4*)&Bs[kk][nt0];
            float av[4] = {a4.x, a4.y, a4.z, a4.w};
            float bv[4] = {b4.x, b4.y, b4.z, b4.w};
            #pragma unroll
            for (int r = 0; r < 4; r++)
                #pragma unroll
                for (int u = 0; u < 4; u++)
                    acc[r][u] = fmaf(av[r], bv[u], acc[r][u]);
        }
        __syncthreads();
    }
    #pragma unroll
    for (int r = 0; r < 4; r++)
        #pragma unroll
        for (int u = 0; u < 4; u++) {
            int n = n0 + nt0 + u;
            C[(m0 + r0 + r) * N + n] = tanhf(acc[r][u] + bias[n]);
        }
}

__global__ void final_logits_kernel(const float* __restrict__ W4,
                                    const float* __restrict__ b4,
                                    float* __restrict__ out) {
    int b    = blockIdx.x;
    int w    = threadIdx.x >> 5;
    int lane = threadIdx.x & 31;
    if (w >= 3) return;
    float sum = 0.0f;
    for (int k = lane; k < 1024; k += 32)
        sum += g_m3[b * 1024 + k] * W4[k * 3 + w];
    #pragma unroll
    for (int off = 16; off; off >>= 1)
        sum += __shfl_down_sync(0xffffffff, sum, off);
    if (lane == 0) out[b * 3 + w] = sum + b4[w];
}

// ---------------------------------------------------------------------------
extern "C" void kernel_launch(void* const* d_in, const int* in_sizes, int n_in,
                              void* d_out, int out_size) {
    const float* premises   = (const float*)d_in[0];
    const float* hypotheses = (const float*)d_in[1];
    const int*   plen       = (const int*)d_in[2];
    const int*   hlen       = (const int*)d_in[3];

    WPtrs wp;
    for (int i = 0; i < 4; i++) {
        wp.wx[i]   = (const float*)d_in[4 + 3 * i + 0];
        wp.wh[i]   = (const float*)d_in[4 + 3 * i + 1];
        wp.bias[i] = (const float*)d_in[4 + 3 * i + 2];
    }
    const float* W1 = (const float*)d_in[16];
    const float* b1 = (const float*)d_in[17];
    const float* W2 = (const float*)d_in[18];
    const float* b2 = (const float*)d_in[19];
    const float* W3 = (const float*)d_in[20];
    const float* b3 = (const float*)d_in[21];
    const float* W4 = (const float*)d_in[22];
    const float* b4 = (const float*)d_in[23];
    float* out = (float*)d_out;

    cudaFuncSetAttribute(lstm_step_mma, cudaFuncAttributeMaxDynamicSharedMemorySize,
                         SMEM_TOTAL_STEP);
    cudaFuncSetAttribute(xz_gemm, cudaFuncAttributeMaxDynamicSharedMemorySize,
                         SMEM_XZ);

    {
        long long n = NTOT_;
        preproc_all<<<(unsigned)((n + 255) / 256), 256>>>(premises, hypotheses, wp);
    }

    xz_gemm<<<dim3(32, 2, 4 * TN_), 256, SMEM_XZ>>>();

    dim3 grid(16, 2, 4);
    for (int s = 0; s < TN_; s++)
        lstm_step_mma<<<grid, 512, SMEM_TOTAL_STEP>>>(plen, hlen, s);

    gather_x_kernel<<<(BN_ * FOURH + 255) / 256, 256>>>();
    mlp_gemm_kernel<<<dim3(1024 / BUT, BN_ / BMT), 256>>>(W1, b1, 1);
    mlp_gemm_kernel<<<dim3(1024 / BUT, BN_ / BMT), 256>>>(W2, b2, 2);
    mlp_gemm_kernel<<<dim3(1024 / BUT, BN_ / BMT), 256>>>(W3, b3, 3);
    final_logits_kernel<<<BN_, 96>>>(W4, b4, out);
}